// round 2
// baseline (speedup 1.0000x reference)
#include <cuda_runtime.h>
#include <math_constants.h>

// Jagged log-softmax, round 2:
//  - single online (max,sumexp) read pass fused (was: 2 read passes + 2 reductions)
//  - float4 vectorized loads/stores with scalar head/tail peel
//  - one block reduction over (m, s) pairs, one __syncthreads round fewer

#define THREADS 256
#define NWARPS (THREADS / 32)

// combine two (max, sumexp) partials: s_out = s1*e^{m1-M} + s2*e^{m2-M}
__device__ __forceinline__ void combine_ms(float& m, float& s, float m2, float s2) {
    float M  = fmaxf(m, m2);
    float f1 = (m  == M) ? 1.0f : __expf(m  - M);  // handles m == -inf (s == 0)
    float f2 = (m2 == M) ? 1.0f : __expf(m2 - M);
    s = s * f1 + s2 * f2;
    m = M;
}

__device__ __forceinline__ void online1(float& m, float& s, float x) {
    if (x > m) {            // first element: m=-inf -> s*expf(-inf)=0, +1
        s = s * __expf(m - x) + 1.0f;
        m = x;
    } else {
        s += __expf(x - m);
    }
}

__global__ void __launch_bounds__(THREADS)
jagged_log_softmax_kernel(const float* __restrict__ logits,
                          const int* __restrict__ prefix_sum,
                          float* __restrict__ out) {
    __shared__ float sm_m[NWARPS];
    __shared__ float sm_s[NWARPS];
    __shared__ float s_lse;

    const int seg   = blockIdx.x;
    const int start = (seg == 0) ? 0 : __ldg(&prefix_sum[seg - 1]);
    const int end   = __ldg(&prefix_sum[seg]);
    if (start >= end) return;

    const int tid  = threadIdx.x;
    const int lane = tid & 31;
    const int warp = tid >> 5;

    // alignment split: head [start,astart), float4 body [astart,aend), tail [aend,end)
    int astart = (start + 3) & ~3;
    if (astart > end) astart = end;
    int aend = end & ~3;
    if (aend < astart) aend = astart;

    const float4* __restrict__ logits4 = (const float4*)logits;

    // ---- Pass 1: fused online max + sumexp ----
    float m = -CUDART_INF_F;
    float s = 0.0f;

    for (int i = start + tid; i < astart; i += THREADS)
        online1(m, s, __ldg(&logits[i]));

    for (int i = astart + tid * 4; i < aend; i += THREADS * 4) {
        float4 v = __ldg(&logits4[i >> 2]);
        float vm = fmaxf(fmaxf(v.x, v.y), fmaxf(v.z, v.w));
        if (vm > m) {                       // m=-inf first: s *= expf(-inf)=0
            s *= __expf(m - vm);
            m = vm;
        }
        s += __expf(v.x - m) + __expf(v.y - m) + __expf(v.z - m) + __expf(v.w - m);
    }

    for (int i = aend + tid; i < end; i += THREADS)
        online1(m, s, __ldg(&logits[i]));

    // warp reduction of (m, s)
    #pragma unroll
    for (int o = 16; o > 0; o >>= 1) {
        float m2 = __shfl_xor_sync(0xFFFFFFFFu, m, o);
        float s2 = __shfl_xor_sync(0xFFFFFFFFu, s, o);
        combine_ms(m, s, m2, s2);
    }
    if (lane == 0) { sm_m[warp] = m; sm_s[warp] = s; }
    __syncthreads();
    if (warp == 0) {
        float mm = (lane < NWARPS) ? sm_m[lane] : -CUDART_INF_F;
        float ss = (lane < NWARPS) ? sm_s[lane] : 0.0f;
        #pragma unroll
        for (int o = NWARPS / 2; o > 0; o >>= 1) {
            float m2 = __shfl_xor_sync(0xFFFFFFFFu, mm, o);
            float s2 = __shfl_xor_sync(0xFFFFFFFFu, ss, o);
            combine_ms(mm, ss, m2, s2);
        }
        if (lane == 0) s_lse = mm + __logf(ss);
    }
    __syncthreads();
    const float lse = s_lse;

    // ---- Pass 2: write (re-read hits L1) ----
    float4* __restrict__ out4 = (float4*)out;

    for (int i = start + tid; i < astart; i += THREADS)
        out[i] = __ldg(&logits[i]) - lse;

    for (int i = astart + tid * 4; i < aend; i += THREADS * 4) {
        float4 v = __ldg(&logits4[i >> 2]);
        float4 r;
        r.x = v.x - lse; r.y = v.y - lse; r.z = v.z - lse; r.w = v.w - lse;
        out4[i >> 2] = r;
    }

    for (int i = aend + tid; i < end; i += THREADS)
        out[i] = __ldg(&logits[i]) - lse;
}

extern "C" void kernel_launch(void* const* d_in, const int* in_sizes, int n_in,
                              void* d_out, int out_size) {
    const float* logits     = (const float*)d_in[0];
    const int*   prefix_sum = (const int*)d_in[1];
    float*       out        = (float*)d_out;

    const int num_segs = in_sizes[1];
    jagged_log_softmax_kernel<<<num_segs, THREADS>>>(logits, prefix_sum, out);
}